// round 11
// baseline (speedup 1.0000x reference)
#include <cuda_runtime.h>
#include <cuda_bf16.h>
#include <cstdint>

#define N_NODES  100000
#define N_EDGES  1200000
#define D        64
#define N_GRAPHS 256
#define TILE_M   128
#define LDA      68    // fp32 smem leading dim (bank-conflict-free frag loads)
#define LDW      68    // float2 smem leading dim for weight hi/lo pairs

// ---------------- scratch (device globals; no allocation allowed) ----------
__device__ float  g_agg[N_NODES * D];      // 25.6 MB
__device__ float  g_S[N_GRAPHS * D];       // per-graph sum of h2
__device__ int    g_cnt[N_GRAPHS];         // nodes per graph
__device__ float2 g_W2[3 * 4096];          // tf32 hi/lo splits of Wg, Wr, Wi

// ---------------- helpers ---------------------------------------------------
__device__ __forceinline__ uint32_t f2tf(float x) {
    uint32_t r; asm("cvt.rna.tf32.f32 %0, %1;" : "=r"(r) : "f"(x)); return r;
}
__device__ __forceinline__ void mma8(float* c, const uint32_t* a, uint32_t b0, uint32_t b1) {
    asm volatile("mma.sync.aligned.m16n8k8.row.col.f32.tf32.tf32.f32 "
                 "{%0,%1,%2,%3}, {%4,%5,%6,%7}, {%8,%9}, {%0,%1,%2,%3};"
                 : "+f"(c[0]), "+f"(c[1]), "+f"(c[2]), "+f"(c[3])
                 : "r"(a[0]), "r"(a[1]), "r"(a[2]), "r"(a[3]), "r"(b0), "r"(b1));
}

// ---------------- zero scratch ----------------------------------------------
__global__ void k_zero() {
    int i = blockIdx.x * blockDim.x + threadIdx.x;
    float4 z = make_float4(0.f, 0.f, 0.f, 0.f);
    if (i < N_NODES * D / 4)  reinterpret_cast<float4*>(g_agg)[i] = z;
    if (i < N_GRAPHS * D / 4) reinterpret_cast<float4*>(g_S)[i]   = z;
    if (i < N_GRAPHS)         g_cnt[i] = 0;
}

// ---------------- weight split: W -> (tf32 hi, tf32 lo) --------------------
__global__ void k_prep(const float* __restrict__ Wg, const float* __restrict__ Wr,
                       const float* __restrict__ Wi) {
    int i = blockIdx.x * blockDim.x + threadIdx.x;
    if (i >= 3 * 4096) return;
    int sel = i >> 12, j = i & 4095;
    const float* W = sel == 0 ? Wg : (sel == 1 ? Wr : Wi);
    float w = W[j];
    uint32_t hb = f2tf(w);
    float hf = __uint_as_float(hb);
    uint32_t lb = f2tf(w - hf);
    g_W2[i] = make_float2(hf, __uint_as_float(lb));
}

// ---------------- edge scatter: agg[dst] += node_feats[src] ----------------
__global__ void k_edge(const float* __restrict__ x,
                       const int* __restrict__ src,
                       const int* __restrict__ dst) {
    int t = blockIdx.x * blockDim.x + threadIdx.x;
    int e = t >> 4;
    int l = t & 15;
    if (e >= N_EDGES) return;
    int s = __ldg(&src[e]);
    int d = __ldg(&dst[e]);
    float4 v = reinterpret_cast<const float4*>(x)[(size_t)s * 16 + l];
    float4* a = reinterpret_cast<float4*>(g_agg) + (size_t)d * 16 + l;
    asm volatile("red.global.add.v4.f32 [%0], {%1, %2, %3, %4};"
                 :: "l"(a), "f"(v.x), "f"(v.y), "f"(v.z), "f"(v.w) : "memory");
}

// ---------------- fused node pipeline (tensor cores) ------------------------
// h1 = relu(agg@Wg + bg) + relu(x@Wr + br) ; h2 = relu(h1@Wi + bi)
// S[graph] += h2 ; cnt[graph] += 1
// Block: 256 threads (8 warps), 128-node tile. Warp w owns rows [16w,16w+16),
// all 64 cols (8 m16n8k8 atoms). Weights: 2xTF32 (hi/lo), activations: 1xTF32.
__global__ void __launch_bounds__(256) k_node(
        const float* __restrict__ x, const int* __restrict__ gid,
        const float* __restrict__ bg, const float* __restrict__ br,
        const float* __restrict__ bi) {
    extern __shared__ float sm[];
    float*  sA  = sm;                              // TILE_M * LDA
    float*  sX  = sA + TILE_M * LDA;               // TILE_M * LDA
    float2* sW2 = (float2*)(sX + TILE_M * LDA);    // 3 * 64 * LDW
    float*  sb  = (float*)(sW2 + 3 * 64 * LDW);    // 3 * 64

    const int tid = threadIdx.x;
    const int node0 = blockIdx.x * TILE_M;

    // weights (hi/lo) -> smem, padded rows
    #pragma unroll
    for (int u = tid; u < 3 * 4096; u += 256) {
        int sel = u >> 12, j = u & 4095;
        int k = j >> 6, n = j & 63;
        sW2[sel * 64 * LDW + k * LDW + n] = g_W2[u];
    }
    if (tid < 64) { sb[tid] = bg[tid]; sb[64 + tid] = br[tid]; sb[128 + tid] = bi[tid]; }

    // agg / x tiles
    #pragma unroll
    for (int u = tid; u < TILE_M * 16; u += 256) {
        int r = u >> 4, c4 = (u & 15) * 4;
        int node = node0 + r;
        float4 va = make_float4(0.f, 0.f, 0.f, 0.f), vx = va;
        if (node < N_NODES) {
            va = *reinterpret_cast<const float4*>(&g_agg[(size_t)node * 64 + c4]);
            vx = *reinterpret_cast<const float4*>(&x[(size_t)node * 64 + c4]);
        }
        *reinterpret_cast<float4*>(&sA[r * LDA + c4]) = va;
        *reinterpret_cast<float4*>(&sX[r * LDA + c4]) = vx;
    }
    __syncthreads();

    const int warp = tid >> 5, lane = tid & 31;
    const int g = lane >> 2, t = lane & 3;
    const int row0 = warp * 16 + g;                 // rows row0, row0+8
    const float2* sWg2 = sW2;
    const float2* sWr2 = sW2 + 64 * LDW;
    const float2* sWi2 = sW2 + 2 * 64 * LDW;

    // ---- GEMM1 (dual): acc1 = agg@Wg, acc2 = x@Wr ----
    float acc1[8][4], acc2[8][4];
    #pragma unroll
    for (int na = 0; na < 8; na++)
        #pragma unroll
        for (int j = 0; j < 4; j++) { acc1[na][j] = 0.f; acc2[na][j] = 0.f; }

    for (int k0 = 0; k0 < 64; k0 += 8) {
        uint32_t aA[4], aX[4];
        aA[0] = f2tf(sA[row0 * LDA + k0 + t]);
        aA[1] = f2tf(sA[(row0 + 8) * LDA + k0 + t]);
        aA[2] = f2tf(sA[row0 * LDA + k0 + t + 4]);
        aA[3] = f2tf(sA[(row0 + 8) * LDA + k0 + t + 4]);
        aX[0] = f2tf(sX[row0 * LDA + k0 + t]);
        aX[1] = f2tf(sX[(row0 + 8) * LDA + k0 + t]);
        aX[2] = f2tf(sX[row0 * LDA + k0 + t + 4]);
        aX[3] = f2tf(sX[(row0 + 8) * LDA + k0 + t + 4]);
        #pragma unroll
        for (int na = 0; na < 8; na++) {
            int n = na * 8 + g;
            float2 w0 = sWg2[(k0 + t) * LDW + n];
            float2 w1 = sWg2[(k0 + t + 4) * LDW + n];
            mma8(acc1[na], aA, __float_as_uint(w0.x), __float_as_uint(w1.x));
            mma8(acc1[na], aA, __float_as_uint(w0.y), __float_as_uint(w1.y));
            float2 v0 = sWr2[(k0 + t) * LDW + n];
            float2 v1 = sWr2[(k0 + t + 4) * LDW + n];
            mma8(acc2[na], aX, __float_as_uint(v0.x), __float_as_uint(v1.x));
            mma8(acc2[na], aX, __float_as_uint(v0.y), __float_as_uint(v1.y));
        }
    }

    // ---- epilogue1: h1 = relu(acc1+bg) + relu(acc2+br), stage into sA ----
    float h1v[8][4];
    #pragma unroll
    for (int na = 0; na < 8; na++) {
        int c0 = na * 8 + 2 * t, c1 = c0 + 1;
        h1v[na][0] = fmaxf(acc1[na][0] + sb[c0], 0.f) + fmaxf(acc2[na][0] + sb[64 + c0], 0.f);
        h1v[na][1] = fmaxf(acc1[na][1] + sb[c1], 0.f) + fmaxf(acc2[na][1] + sb[64 + c1], 0.f);
        h1v[na][2] = fmaxf(acc1[na][2] + sb[c0], 0.f) + fmaxf(acc2[na][2] + sb[64 + c0], 0.f);
        h1v[na][3] = fmaxf(acc1[na][3] + sb[c1], 0.f) + fmaxf(acc2[na][3] + sb[64 + c1], 0.f);
    }
    __syncthreads();
    #pragma unroll
    for (int na = 0; na < 8; na++) {
        int c0 = na * 8 + 2 * t;
        *reinterpret_cast<float2*>(&sA[row0 * LDA + c0])       = make_float2(h1v[na][0], h1v[na][1]);
        *reinterpret_cast<float2*>(&sA[(row0 + 8) * LDA + c0]) = make_float2(h1v[na][2], h1v[na][3]);
    }
    __syncthreads();

    // ---- GEMM2: h2 = relu(h1@Wi + bi) ----
    float acc[8][4];
    #pragma unroll
    for (int na = 0; na < 8; na++)
        #pragma unroll
        for (int j = 0; j < 4; j++) acc[na][j] = 0.f;

    for (int k0 = 0; k0 < 64; k0 += 8) {
        uint32_t aH[4];
        aH[0] = f2tf(sA[row0 * LDA + k0 + t]);
        aH[1] = f2tf(sA[(row0 + 8) * LDA + k0 + t]);
        aH[2] = f2tf(sA[row0 * LDA + k0 + t + 4]);
        aH[3] = f2tf(sA[(row0 + 8) * LDA + k0 + t + 4]);
        #pragma unroll
        for (int na = 0; na < 8; na++) {
            int n = na * 8 + g;
            float2 w0 = sWi2[(k0 + t) * LDW + n];
            float2 w1 = sWi2[(k0 + t + 4) * LDW + n];
            mma8(acc[na], aH, __float_as_uint(w0.x), __float_as_uint(w1.x));
            mma8(acc[na], aH, __float_as_uint(w0.y), __float_as_uint(w1.y));
        }
    }

    // ---- epilogue2: scatter h2 into per-graph sums ----
    int nA = node0 + row0, nB = nA + 8;
    int gdA = (nA < N_NODES) ? __ldg(&gid[nA]) : 0;
    int gdB = (nB < N_NODES) ? __ldg(&gid[nB]) : 0;
    #pragma unroll
    for (int na = 0; na < 8; na++) {
        int c0 = na * 8 + 2 * t, c1 = c0 + 1;
        if (nA < N_NODES) {
            float p0 = fmaxf(acc[na][0] + sb[128 + c0], 0.f);
            float p1 = fmaxf(acc[na][1] + sb[128 + c1], 0.f);
            asm volatile("red.global.add.v2.f32 [%0], {%1, %2};"
                         :: "l"(&g_S[gdA * 64 + c0]), "f"(p0), "f"(p1) : "memory");
        }
        if (nB < N_NODES) {
            float p2 = fmaxf(acc[na][2] + sb[128 + c0], 0.f);
            float p3 = fmaxf(acc[na][3] + sb[128 + c1], 0.f);
            asm volatile("red.global.add.v2.f32 [%0], {%1, %2};"
                         :: "l"(&g_S[gdB * 64 + c0]), "f"(p2), "f"(p3) : "memory");
        }
    }
    if (t == 0) {
        if (nA < N_NODES) atomicAdd(&g_cnt[gdA], 1);
        if (nB < N_NODES) atomicAdd(&g_cnt[gdB], 1);
    }
}

// ---------------- final readout ---------------------------------------------
// out[g] = S[g] . (W_out @ W_pred) + cnt[g] * (b_out . W_pred) + b_pred
__global__ void __launch_bounds__(64) k_final(const float* __restrict__ Wo,
                                              const float* __restrict__ bo,
                                              const float* __restrict__ Wp,
                                              const float* __restrict__ bp,
                                              float* __restrict__ out) {
    __shared__ float red[4];
    int gr = blockIdx.x, k = threadIdx.x;   // k in [0,64)
    float wop = 0.f;
    #pragma unroll 16
    for (int m = 0; m < 128; m++) wop += __ldg(&Wo[k * 128 + m]) * __ldg(&Wp[m]);
    float p  = g_S[gr * 64 + k] * wop;
    float sc = bo[k] * Wp[k] + bo[k + 64] * Wp[k + 64];
    #pragma unroll
    for (int o = 16; o; o >>= 1) {
        p  += __shfl_xor_sync(0xffffffffu, p, o);
        sc += __shfl_xor_sync(0xffffffffu, sc, o);
    }
    if ((k & 31) == 0) { red[(k >> 5) * 2] = p; red[(k >> 5) * 2 + 1] = sc; }
    __syncthreads();
    if (k == 0)
        out[gr] = red[0] + red[2] + (float)g_cnt[gr] * (red[1] + red[3]) + bp[0];
}

// ---------------- launch ----------------------------------------------------
extern "C" void kernel_launch(void* const* d_in, const int* in_sizes, int n_in,
                              void* d_out, int out_size) {
    const float* node_feats = (const float*)d_in[0];
    // d_in[1] = edge_feats (unused by the reference)
    const int*   src = (const int*)d_in[2];
    const int*   dst = (const int*)d_in[3];
    const int*   gid = (const int*)d_in[4];
    const float* Wg  = (const float*)d_in[5];
    const float* bg  = (const float*)d_in[6];
    const float* Wr  = (const float*)d_in[7];
    const float* br  = (const float*)d_in[8];
    const float* Wi  = (const float*)d_in[9];
    const float* bi  = (const float*)d_in[10];
    const float* Wo  = (const float*)d_in[11];
    const float* bo  = (const float*)d_in[12];
    const float* Wp  = (const float*)d_in[13];
    const float* bp  = (const float*)d_in[14];
    float* out = (float*)d_out;

    const int smem_bytes = (2 * TILE_M * LDA) * 4 + (3 * 64 * LDW) * 8 + 192 * 4;
    static int configured = 0;
    cudaFuncSetAttribute(k_node, cudaFuncAttributeMaxDynamicSharedMemorySize, smem_bytes);
    (void)configured;

    k_zero<<<(N_NODES * D / 4 + 255) / 256, 256>>>();
    k_prep<<<48, 256>>>(Wg, Wr, Wi);
    k_edge<<<(N_EDGES * 16) / 256, 256>>>(node_feats, src, dst);
    k_node<<<(N_NODES + TILE_M - 1) / TILE_M, 256, smem_bytes>>>(node_feats, gid, bg, br, bi);
    k_final<<<N_GRAPHS, 64>>>(Wo, bo, Wp, bp, out);
}

// round 12
// speedup vs baseline: 1.0002x; 1.0002x over previous
#include <cuda_runtime.h>
#include <cuda_bf16.h>
#include <cstdint>

#define N_NODES  100000
#define N_EDGES  1200000
#define D        64
#define N_GRAPHS 256
#define TILE_M   128
#define LDA      68    // fp32 smem leading dim (bank-conflict-free frag loads)
#define LDW      68    // float2 smem leading dim for weight hi/lo pairs

// ---------------- scratch (device globals; no allocation allowed) ----------
__device__ float  g_agg[N_NODES * D];      // 25.6 MB
__device__ float  g_S[N_GRAPHS * D];       // per-graph sum of h2
__device__ int    g_cnt[N_GRAPHS];         // nodes per graph
__device__ float2 g_W2[3 * 4096];          // tf32 hi/lo splits of Wg, Wr, Wi

// ---------------- helpers ---------------------------------------------------
__device__ __forceinline__ uint32_t f2tf(float x) {
    uint32_t r; asm("cvt.rna.tf32.f32 %0, %1;" : "=r"(r) : "f"(x)); return r;
}
__device__ __forceinline__ void mma8(float* c, const uint32_t* a, uint32_t b0, uint32_t b1) {
    asm volatile("mma.sync.aligned.m16n8k8.row.col.f32.tf32.tf32.f32 "
                 "{%0,%1,%2,%3}, {%4,%5,%6,%7}, {%8,%9}, {%0,%1,%2,%3};"
                 : "+f"(c[0]), "+f"(c[1]), "+f"(c[2]), "+f"(c[3])
                 : "r"(a[0]), "r"(a[1]), "r"(a[2]), "r"(a[3]), "r"(b0), "r"(b1));
}

// ---------------- zero scratch ----------------------------------------------
__global__ void k_zero() {
    int i = blockIdx.x * blockDim.x + threadIdx.x;
    float4 z = make_float4(0.f, 0.f, 0.f, 0.f);
    if (i < N_NODES * D / 4)  reinterpret_cast<float4*>(g_agg)[i] = z;
    if (i < N_GRAPHS * D / 4) reinterpret_cast<float4*>(g_S)[i]   = z;
    if (i < N_GRAPHS)         g_cnt[i] = 0;
}

// ---------------- weight split: W -> (tf32 hi, tf32 lo) --------------------
__global__ void k_prep(const float* __restrict__ Wg, const float* __restrict__ Wr,
                       const float* __restrict__ Wi) {
    int i = blockIdx.x * blockDim.x + threadIdx.x;
    if (i >= 3 * 4096) return;
    int sel = i >> 12, j = i & 4095;
    const float* W = sel == 0 ? Wg : (sel == 1 ? Wr : Wi);
    float w = W[j];
    uint32_t hb = f2tf(w);
    float hf = __uint_as_float(hb);
    uint32_t lb = f2tf(w - hf);
    g_W2[i] = make_float2(hf, __uint_as_float(lb));
}

// ---------------- edge scatter: agg[dst] += node_feats[src] ----------------
__global__ void k_edge(const float* __restrict__ x,
                       const int* __restrict__ src,
                       const int* __restrict__ dst) {
    int t = blockIdx.x * blockDim.x + threadIdx.x;
    int e = t >> 4;
    int l = t & 15;
    if (e >= N_EDGES) return;
    int s = __ldg(&src[e]);
    int d = __ldg(&dst[e]);
    float4 v = reinterpret_cast<const float4*>(x)[(size_t)s * 16 + l];
    float4* a = reinterpret_cast<float4*>(g_agg) + (size_t)d * 16 + l;
    asm volatile("red.global.add.v4.f32 [%0], {%1, %2, %3, %4};"
                 :: "l"(a), "f"(v.x), "f"(v.y), "f"(v.z), "f"(v.w) : "memory");
}

// ---------------- fused node pipeline (tensor cores) ------------------------
// h1 = relu(agg@Wg + bg) + relu(x@Wr + br) ; h2 = relu(h1@Wi + bi)
// S[graph] += h2 ; cnt[graph] += 1
// Block: 256 threads (8 warps), 128-node tile. Warp w owns rows [16w,16w+16),
// all 64 cols (8 m16n8k8 atoms). Weights: 2xTF32 (hi/lo), activations: 1xTF32.
__global__ void __launch_bounds__(256) k_node(
        const float* __restrict__ x, const int* __restrict__ gid,
        const float* __restrict__ bg, const float* __restrict__ br,
        const float* __restrict__ bi) {
    extern __shared__ float sm[];
    float*  sA  = sm;                              // TILE_M * LDA
    float*  sX  = sA + TILE_M * LDA;               // TILE_M * LDA
    float2* sW2 = (float2*)(sX + TILE_M * LDA);    // 3 * 64 * LDW
    float*  sb  = (float*)(sW2 + 3 * 64 * LDW);    // 3 * 64

    const int tid = threadIdx.x;
    const int node0 = blockIdx.x * TILE_M;

    // weights (hi/lo) -> smem, padded rows
    #pragma unroll
    for (int u = tid; u < 3 * 4096; u += 256) {
        int sel = u >> 12, j = u & 4095;
        int k = j >> 6, n = j & 63;
        sW2[sel * 64 * LDW + k * LDW + n] = g_W2[u];
    }
    if (tid < 64) { sb[tid] = bg[tid]; sb[64 + tid] = br[tid]; sb[128 + tid] = bi[tid]; }

    // agg / x tiles
    #pragma unroll
    for (int u = tid; u < TILE_M * 16; u += 256) {
        int r = u >> 4, c4 = (u & 15) * 4;
        int node = node0 + r;
        float4 va = make_float4(0.f, 0.f, 0.f, 0.f), vx = va;
        if (node < N_NODES) {
            va = *reinterpret_cast<const float4*>(&g_agg[(size_t)node * 64 + c4]);
            vx = *reinterpret_cast<const float4*>(&x[(size_t)node * 64 + c4]);
        }
        *reinterpret_cast<float4*>(&sA[r * LDA + c4]) = va;
        *reinterpret_cast<float4*>(&sX[r * LDA + c4]) = vx;
    }
    __syncthreads();

    const int warp = tid >> 5, lane = tid & 31;
    const int g = lane >> 2, t = lane & 3;
    const int row0 = warp * 16 + g;                 // rows row0, row0+8
    const float2* sWg2 = sW2;
    const float2* sWr2 = sW2 + 64 * LDW;
    const float2* sWi2 = sW2 + 2 * 64 * LDW;

    // ---- GEMM1 (dual): acc1 = agg@Wg, acc2 = x@Wr ----
    float acc1[8][4], acc2[8][4];
    #pragma unroll
    for (int na = 0; na < 8; na++)
        #pragma unroll
        for (int j = 0; j < 4; j++) { acc1[na][j] = 0.f; acc2[na][j] = 0.f; }

    for (int k0 = 0; k0 < 64; k0 += 8) {
        uint32_t aA[4], aX[4];
        aA[0] = f2tf(sA[row0 * LDA + k0 + t]);
        aA[1] = f2tf(sA[(row0 + 8) * LDA + k0 + t]);
        aA[2] = f2tf(sA[row0 * LDA + k0 + t + 4]);
        aA[3] = f2tf(sA[(row0 + 8) * LDA + k0 + t + 4]);
        aX[0] = f2tf(sX[row0 * LDA + k0 + t]);
        aX[1] = f2tf(sX[(row0 + 8) * LDA + k0 + t]);
        aX[2] = f2tf(sX[row0 * LDA + k0 + t + 4]);
        aX[3] = f2tf(sX[(row0 + 8) * LDA + k0 + t + 4]);
        #pragma unroll
        for (int na = 0; na < 8; na++) {
            int n = na * 8 + g;
            float2 w0 = sWg2[(k0 + t) * LDW + n];
            float2 w1 = sWg2[(k0 + t + 4) * LDW + n];
            mma8(acc1[na], aA, __float_as_uint(w0.x), __float_as_uint(w1.x));
            mma8(acc1[na], aA, __float_as_uint(w0.y), __float_as_uint(w1.y));
            float2 v0 = sWr2[(k0 + t) * LDW + n];
            float2 v1 = sWr2[(k0 + t + 4) * LDW + n];
            mma8(acc2[na], aX, __float_as_uint(v0.x), __float_as_uint(v1.x));
            mma8(acc2[na], aX, __float_as_uint(v0.y), __float_as_uint(v1.y));
        }
    }

    // ---- epilogue1: h1 = relu(acc1+bg) + relu(acc2+br), stage into sA ----
    float h1v[8][4];
    #pragma unroll
    for (int na = 0; na < 8; na++) {
        int c0 = na * 8 + 2 * t, c1 = c0 + 1;
        h1v[na][0] = fmaxf(acc1[na][0] + sb[c0], 0.f) + fmaxf(acc2[na][0] + sb[64 + c0], 0.f);
        h1v[na][1] = fmaxf(acc1[na][1] + sb[c1], 0.f) + fmaxf(acc2[na][1] + sb[64 + c1], 0.f);
        h1v[na][2] = fmaxf(acc1[na][2] + sb[c0], 0.f) + fmaxf(acc2[na][2] + sb[64 + c0], 0.f);
        h1v[na][3] = fmaxf(acc1[na][3] + sb[c1], 0.f) + fmaxf(acc2[na][3] + sb[64 + c1], 0.f);
    }
    __syncthreads();
    #pragma unroll
    for (int na = 0; na < 8; na++) {
        int c0 = na * 8 + 2 * t;
        *reinterpret_cast<float2*>(&sA[row0 * LDA + c0])       = make_float2(h1v[na][0], h1v[na][1]);
        *reinterpret_cast<float2*>(&sA[(row0 + 8) * LDA + c0]) = make_float2(h1v[na][2], h1v[na][3]);
    }
    __syncthreads();

    // ---- GEMM2: h2 = relu(h1@Wi + bi) ----
    float acc[8][4];
    #pragma unroll
    for (int na = 0; na < 8; na++)
        #pragma unroll
        for (int j = 0; j < 4; j++) acc[na][j] = 0.f;

    for (int k0 = 0; k0 < 64; k0 += 8) {
        uint32_t aH[4];
        aH[0] = f2tf(sA[row0 * LDA + k0 + t]);
        aH[1] = f2tf(sA[(row0 + 8) * LDA + k0 + t]);
        aH[2] = f2tf(sA[row0 * LDA + k0 + t + 4]);
        aH[3] = f2tf(sA[(row0 + 8) * LDA + k0 + t + 4]);
        #pragma unroll
        for (int na = 0; na < 8; na++) {
            int n = na * 8 + g;
            float2 w0 = sWi2[(k0 + t) * LDW + n];
            float2 w1 = sWi2[(k0 + t + 4) * LDW + n];
            mma8(acc[na], aH, __float_as_uint(w0.x), __float_as_uint(w1.x));
            mma8(acc[na], aH, __float_as_uint(w0.y), __float_as_uint(w1.y));
        }
    }

    // ---- epilogue2: scatter h2 into per-graph sums ----
    int nA = node0 + row0, nB = nA + 8;
    int gdA = (nA < N_NODES) ? __ldg(&gid[nA]) : 0;
    int gdB = (nB < N_NODES) ? __ldg(&gid[nB]) : 0;
    #pragma unroll
    for (int na = 0; na < 8; na++) {
        int c0 = na * 8 + 2 * t, c1 = c0 + 1;
        if (nA < N_NODES) {
            float p0 = fmaxf(acc[na][0] + sb[128 + c0], 0.f);
            float p1 = fmaxf(acc[na][1] + sb[128 + c1], 0.f);
            asm volatile("red.global.add.v2.f32 [%0], {%1, %2};"
                         :: "l"(&g_S[gdA * 64 + c0]), "f"(p0), "f"(p1) : "memory");
        }
        if (nB < N_NODES) {
            float p2 = fmaxf(acc[na][2] + sb[128 + c0], 0.f);
            float p3 = fmaxf(acc[na][3] + sb[128 + c1], 0.f);
            asm volatile("red.global.add.v2.f32 [%0], {%1, %2};"
                         :: "l"(&g_S[gdB * 64 + c0]), "f"(p2), "f"(p3) : "memory");
        }
    }
    if (t == 0) {
        if (nA < N_NODES) atomicAdd(&g_cnt[gdA], 1);
        if (nB < N_NODES) atomicAdd(&g_cnt[gdB], 1);
    }
}

// ---------------- final readout ---------------------------------------------
// out[g] = S[g] . (W_out @ W_pred) + cnt[g] * (b_out . W_pred) + b_pred
__global__ void __launch_bounds__(64) k_final(const float* __restrict__ Wo,
                                              const float* __restrict__ bo,
                                              const float* __restrict__ Wp,
                                              const float* __restrict__ bp,
                                              float* __restrict__ out) {
    __shared__ float red[4];
    int gr = blockIdx.x, k = threadIdx.x;   // k in [0,64)
    float wop = 0.f;
    #pragma unroll 16
    for (int m = 0; m < 128; m++) wop += __ldg(&Wo[k * 128 + m]) * __ldg(&Wp[m]);
    float p  = g_S[gr * 64 + k] * wop;
    float sc = bo[k] * Wp[k] + bo[k + 64] * Wp[k + 64];
    #pragma unroll
    for (int o = 16; o; o >>= 1) {
        p  += __shfl_xor_sync(0xffffffffu, p, o);
        sc += __shfl_xor_sync(0xffffffffu, sc, o);
    }
    if ((k & 31) == 0) { red[(k >> 5) * 2] = p; red[(k >> 5) * 2 + 1] = sc; }
    __syncthreads();
    if (k == 0)
        out[gr] = red[0] + red[2] + (float)g_cnt[gr] * (red[1] + red[3]) + bp[0];
}

// ---------------- launch ----------------------------------------------------
extern "C" void kernel_launch(void* const* d_in, const int* in_sizes, int n_in,
                              void* d_out, int out_size) {
    const float* node_feats = (const float*)d_in[0];
    // d_in[1] = edge_feats (unused by the reference)
    const int*   src = (const int*)d_in[2];
    const int*   dst = (const int*)d_in[3];
    const int*   gid = (const int*)d_in[4];
    const float* Wg  = (const float*)d_in[5];
    const float* bg  = (const float*)d_in[6];
    const float* Wr  = (const float*)d_in[7];
    const float* br  = (const float*)d_in[8];
    const float* Wi  = (const float*)d_in[9];
    const float* bi  = (const float*)d_in[10];
    const float* Wo  = (const float*)d_in[11];
    const float* bo  = (const float*)d_in[12];
    const float* Wp  = (const float*)d_in[13];
    const float* bp  = (const float*)d_in[14];
    float* out = (float*)d_out;

    const int smem_bytes = (2 * TILE_M * LDA) * 4 + (3 * 64 * LDW) * 8 + 192 * 4;
    static int configured = 0;
    cudaFuncSetAttribute(k_node, cudaFuncAttributeMaxDynamicSharedMemorySize, smem_bytes);
    (void)configured;

    k_zero<<<(N_NODES * D / 4 + 255) / 256, 256>>>();
    k_prep<<<48, 256>>>(Wg, Wr, Wi);
    k_edge<<<(N_EDGES * 16) / 256, 256>>>(node_feats, src, dst);
    k_node<<<(N_NODES + TILE_M - 1) / TILE_M, 256, smem_bytes>>>(node_feats, gid, bg, br, bi);
    k_final<<<N_GRAPHS, 64>>>(Wo, bo, Wp, bp, out);
}

// round 13
// speedup vs baseline: 1.1042x; 1.1039x over previous
#include <cuda_runtime.h>
#include <cuda_bf16.h>
#include <cstdint>

#define N_NODES  100000
#define N_EDGES  1200000
#define D        64
#define N_GRAPHS 256
#define TILE_M   128
#define LDA      68    // fp32 smem leading dim for act/h1 tile (conflict-free)

// ---------------- scratch (device globals; no allocation allowed) ----------
__device__ float    g_agg[N_NODES * D];    // 25.6 MB
__device__ float    g_S[N_GRAPHS * D];     // per-graph sum of h2
__device__ int      g_cnt[N_GRAPHS];       // nodes per graph
__device__ uint32_t g_Wp[3 * 4096];        // packed bf16 (hi<<16|lo), XOR-swizzled

// ---------------- helpers ---------------------------------------------------
__device__ __forceinline__ uint32_t f2tf(float x) {
    uint32_t r; asm("cvt.rna.tf32.f32 %0, %1;" : "=r"(r) : "f"(x)); return r;
}
__device__ __forceinline__ void mma8(float* c, const uint32_t* a, uint32_t b0, uint32_t b1) {
    asm volatile("mma.sync.aligned.m16n8k8.row.col.f32.tf32.tf32.f32 "
                 "{%0,%1,%2,%3}, {%4,%5,%6,%7}, {%8,%9}, {%0,%1,%2,%3};"
                 : "+f"(c[0]), "+f"(c[1]), "+f"(c[2]), "+f"(c[3])
                 : "r"(a[0]), "r"(a[1]), "r"(a[2]), "r"(a[3]), "r"(b0), "r"(b1));
}

// ---------------- zero scratch ----------------------------------------------
__global__ void k_zero() {
    int i = blockIdx.x * blockDim.x + threadIdx.x;
    float4 z = make_float4(0.f, 0.f, 0.f, 0.f);
    if (i < N_NODES * D / 4)  reinterpret_cast<float4*>(g_agg)[i] = z;
    if (i < N_GRAPHS * D / 4) reinterpret_cast<float4*>(g_S)[i]   = z;
    if (i < N_GRAPHS)         g_cnt[i] = 0;
}

// ---------------- weight prep: bf16 hi/lo pack + XOR bank swizzle -----------
// g_Wp[sel*4096 + k*64 + j] = pack(W[k][ j ^ ((k&3)<<3) ])
__global__ void k_prep(const float* __restrict__ Wg, const float* __restrict__ Wr,
                       const float* __restrict__ Wi) {
    int i = blockIdx.x * blockDim.x + threadIdx.x;
    if (i >= 3 * 4096) return;
    int sel = i >> 12, j = i & 4095;
    int k = j >> 6, n0 = j & 63;
    int n = n0 ^ ((k & 3) << 3);
    const float* W = sel == 0 ? Wg : (sel == 1 ? Wr : Wi);
    float w = W[k * 64 + n];
    __nv_bfloat16 hb = __float2bfloat16(w);
    float hf = __bfloat162float(hb);
    __nv_bfloat16 lb = __float2bfloat16(w - hf);
    uint32_t hi16 = ((uint32_t)__bfloat16_as_ushort(hb)) << 16;
    uint32_t lo16 = (uint32_t)__bfloat16_as_ushort(lb);
    g_Wp[i] = hi16 | lo16;
}

// ---------------- edge scatter: agg[dst] += node_feats[src] ----------------
__global__ void k_edge(const float* __restrict__ x,
                       const int* __restrict__ src,
                       const int* __restrict__ dst) {
    int t = blockIdx.x * blockDim.x + threadIdx.x;
    int e = t >> 4;
    int l = t & 15;
    if (e >= N_EDGES) return;
    int s = __ldg(&src[e]);
    int d = __ldg(&dst[e]);
    float4 v = reinterpret_cast<const float4*>(x)[(size_t)s * 16 + l];
    float4* a = reinterpret_cast<float4*>(g_agg) + (size_t)d * 16 + l;
    asm volatile("red.global.add.v4.f32 [%0], {%1, %2, %3, %4};"
                 :: "l"(a), "f"(v.x), "f"(v.y), "f"(v.z), "f"(v.w) : "memory");
}

// ---------------- fused node pipeline (tensor cores) ------------------------
// h1 = relu(agg@Wg + bg) + relu(x@Wr + br) ; h2 = relu(h1@Wi + bi)
// S[graph] += h2 ; cnt[graph] += 1
// 256 thr / 8 warps, 128-node tile, warp w owns rows [16w,16w+16).
// Weights: packed bf16 hi/lo in smem (swizzled). agg staged in smem (reused
// as h1 buffer); x A-frags loaded directly from global (L2-resident).
__global__ void __launch_bounds__(256, 2) k_node(
        const float* __restrict__ x, const int* __restrict__ gid,
        const float* __restrict__ bg, const float* __restrict__ br,
        const float* __restrict__ bi) {
    extern __shared__ float sm[];
    uint32_t* sW = (uint32_t*)sm;                  // 3*4096 packed weights
    float*    sH = sm + 3 * 4096;                  // TILE_M * LDA (agg, then h1)
    float*    sb = sH + TILE_M * LDA;              // 3 * 64 biases

    const int tid = threadIdx.x;
    const int node0 = blockIdx.x * TILE_M;

    // packed weights -> smem (uint4 copies)
    #pragma unroll
    for (int u = tid; u < 3 * 1024; u += 256)
        reinterpret_cast<uint4*>(sW)[u] = reinterpret_cast<const uint4*>(g_Wp)[u];
    if (tid < 64) { sb[tid] = bg[tid]; sb[64 + tid] = br[tid]; sb[128 + tid] = bi[tid]; }

    // agg tile -> smem (padded rows)
    #pragma unroll
    for (int u = tid; u < TILE_M * 16; u += 256) {
        int r = u >> 4, c4 = (u & 15) * 4;
        int node = node0 + r;
        float4 va = make_float4(0.f, 0.f, 0.f, 0.f);
        if (node < N_NODES)
            va = *reinterpret_cast<const float4*>(&g_agg[(size_t)node * 64 + c4]);
        *reinterpret_cast<float4*>(&sH[r * LDA + c4]) = va;
    }
    __syncthreads();

    const int warp = tid >> 5, lane = tid & 31;
    const int g = lane >> 2, t = lane & 3;
    const int row0 = warp * 16 + g;                // rows row0, row0+8
    const uint32_t* sWg = sW;
    const uint32_t* sWr = sW + 4096;
    const uint32_t* sWi = sW + 2 * 4096;

    const int nA = node0 + row0, nB = nA + 8;      // global node ids of this lane's rows
    const bool vA = (nA < N_NODES), vB = (nB < N_NODES);
    const float* xA = x + (size_t)(vA ? nA : 0) * 64;
    const float* xB = x + (size_t)(vB ? nB : 0) * 64;

    // ---- GEMM1 (dual): acc1 = agg@Wg, acc2 = x@Wr ----
    float acc1[8][4], acc2[8][4];
    #pragma unroll
    for (int na = 0; na < 8; na++)
        #pragma unroll
        for (int j = 0; j < 4; j++) { acc1[na][j] = 0.f; acc2[na][j] = 0.f; }

    #pragma unroll
    for (int k0 = 0; k0 < 64; k0 += 8) {
        uint32_t aA[4], aX[4];
        aA[0] = f2tf(sH[row0 * LDA + k0 + t]);
        aA[1] = f2tf(sH[(row0 + 8) * LDA + k0 + t]);
        aA[2] = f2tf(sH[row0 * LDA + k0 + t + 4]);
        aA[3] = f2tf(sH[(row0 + 8) * LDA + k0 + t + 4]);
        float x0 = vA ? __ldg(&xA[k0 + t])     : 0.f;
        float x1 = vB ? __ldg(&xB[k0 + t])     : 0.f;
        float x2 = vA ? __ldg(&xA[k0 + t + 4]) : 0.f;
        float x3 = vB ? __ldg(&xB[k0 + t + 4]) : 0.f;
        aX[0] = f2tf(x0); aX[1] = f2tf(x1); aX[2] = f2tf(x2); aX[3] = f2tf(x3);
        #pragma unroll
        for (int na = 0; na < 8; na++) {
            int col = ((na ^ t) << 3) + g;         // swizzled column
            uint32_t wg0 = sWg[(k0 + t) * 64 + col];
            uint32_t wg1 = sWg[(k0 + t + 4) * 64 + col];
            uint32_t wr0 = sWr[(k0 + t) * 64 + col];
            uint32_t wr1 = sWr[(k0 + t + 4) * 64 + col];
            mma8(acc1[na], aA, wg0 & 0xFFFF0000u, wg1 & 0xFFFF0000u);
            mma8(acc1[na], aA, wg0 << 16,         wg1 << 16);
            mma8(acc2[na], aX, wr0 & 0xFFFF0000u, wr1 & 0xFFFF0000u);
            mma8(acc2[na], aX, wr0 << 16,         wr1 << 16);
        }
    }

    // ---- epilogue1: h1 = relu(acc1+bg) + relu(acc2+br) -> sH (own band) ----
    __syncwarp();   // all of this warp's reads of its sH band are done
    #pragma unroll
    for (int na = 0; na < 8; na++) {
        int c0 = na * 8 + 2 * t, c1 = c0 + 1;
        float v0 = fmaxf(acc1[na][0] + sb[c0], 0.f) + fmaxf(acc2[na][0] + sb[64 + c0], 0.f);
        float v1 = fmaxf(acc1[na][1] + sb[c1], 0.f) + fmaxf(acc2[na][1] + sb[64 + c1], 0.f);
        float v2 = fmaxf(acc1[na][2] + sb[c0], 0.f) + fmaxf(acc2[na][2] + sb[64 + c0], 0.f);
        float v3 = fmaxf(acc1[na][3] + sb[c1], 0.f) + fmaxf(acc2[na][3] + sb[64 + c1], 0.f);
        *reinterpret_cast<float2*>(&sH[row0 * LDA + c0])       = make_float2(v0, v1);
        *reinterpret_cast<float2*>(&sH[(row0 + 8) * LDA + c0]) = make_float2(v2, v3);
    }
    __syncwarp();

    // ---- GEMM2: h2 = relu(h1@Wi + bi) ----
    float acc[8][4];
    #pragma unroll
    for (int na = 0; na < 8; na++)
        #pragma unroll
        for (int j = 0; j < 4; j++) acc[na][j] = 0.f;

    #pragma unroll
    for (int k0 = 0; k0 < 64; k0 += 8) {
        uint32_t aH[4];
        aH[0] = f2tf(sH[row0 * LDA + k0 + t]);
        aH[1] = f2tf(sH[(row0 + 8) * LDA + k0 + t]);
        aH[2] = f2tf(sH[row0 * LDA + k0 + t + 4]);
        aH[3] = f2tf(sH[(row0 + 8) * LDA + k0 + t + 4]);
        #pragma unroll
        for (int na = 0; na < 8; na++) {
            int col = ((na ^ t) << 3) + g;
            uint32_t wi0 = sWi[(k0 + t) * 64 + col];
            uint32_t wi1 = sWi[(k0 + t + 4) * 64 + col];
            mma8(acc[na], aH, wi0 & 0xFFFF0000u, wi1 & 0xFFFF0000u);
            mma8(acc[na], aH, wi0 << 16,         wi1 << 16);
        }
    }

    // ---- epilogue2: scatter h2 into per-graph sums ----
    int gdA = vA ? __ldg(&gid[nA]) : 0;
    int gdB = vB ? __ldg(&gid[nB]) : 0;
    #pragma unroll
    for (int na = 0; na < 8; na++) {
        int c0 = na * 8 + 2 * t, c1 = c0 + 1;
        if (vA) {
            float p0 = fmaxf(acc[na][0] + sb[128 + c0], 0.f);
            float p1 = fmaxf(acc[na][1] + sb[128 + c1], 0.f);
            asm volatile("red.global.add.v2.f32 [%0], {%1, %2};"
                         :: "l"(&g_S[gdA * 64 + c0]), "f"(p0), "f"(p1) : "memory");
        }
        if (vB) {
            float p2 = fmaxf(acc[na][2] + sb[128 + c0], 0.f);
            float p3 = fmaxf(acc[na][3] + sb[128 + c1], 0.f);
            asm volatile("red.global.add.v2.f32 [%0], {%1, %2};"
                         :: "l"(&g_S[gdB * 64 + c0]), "f"(p2), "f"(p3) : "memory");
        }
    }
    if (t == 0) {
        if (vA) atomicAdd(&g_cnt[gdA], 1);
        if (vB) atomicAdd(&g_cnt[gdB], 1);
    }
}

// ---------------- final readout ---------------------------------------------
// out[g] = S[g] . (W_out @ W_pred) + cnt[g] * (b_out . W_pred) + b_pred
__global__ void __launch_bounds__(64) k_final(const float* __restrict__ Wo,
                                              const float* __restrict__ bo,
                                              const float* __restrict__ Wp,
                                              const float* __restrict__ bp,
                                              float* __restrict__ out) {
    __shared__ float red[4];
    int gr = blockIdx.x, k = threadIdx.x;   // k in [0,64)
    float wop = 0.f;
    #pragma unroll 16
    for (int m = 0; m < 128; m++) wop += __ldg(&Wo[k * 128 + m]) * __ldg(&Wp[m]);
    float p  = g_S[gr * 64 + k] * wop;
    float sc = bo[k] * Wp[k] + bo[k + 64] * Wp[k + 64];
    #pragma unroll
    for (int o = 16; o; o >>= 1) {
        p  += __shfl_xor_sync(0xffffffffu, p, o);
        sc += __shfl_xor_sync(0xffffffffu, sc, o);
    }
    if ((k & 31) == 0) { red[(k >> 5) * 2] = p; red[(k >> 5) * 2 + 1] = sc; }
    __syncthreads();
    if (k == 0)
        out[gr] = red[0] + red[2] + (float)g_cnt[gr] * (red[1] + red[3]) + bp[0];
}

// ---------------- launch ----------------------------------------------------
extern "C" void kernel_launch(void* const* d_in, const int* in_sizes, int n_in,
                              void* d_out, int out_size) {
    const float* node_feats = (const float*)d_in[0];
    // d_in[1] = edge_feats (unused by the reference)
    const int*   src = (const int*)d_in[2];
    const int*   dst = (const int*)d_in[3];
    const int*   gid = (const int*)d_in[4];
    const float* Wg  = (const float*)d_in[5];
    const float* bg  = (const float*)d_in[6];
    const float* Wr  = (const float*)d_in[7];
    const float* br  = (const float*)d_in[8];
    const float* Wi  = (const float*)d_in[9];
    const float* bi  = (const float*)d_in[10];
    const float* Wo  = (const float*)d_in[11];
    const float* bo  = (const float*)d_in[12];
    const float* Wp  = (const float*)d_in[13];
    const float* bp  = (const float*)d_in[14];
    float* out = (float*)d_out;

    const int smem_bytes = 3 * 4096 * 4 + TILE_M * LDA * 4 + 192 * 4;
    cudaFuncSetAttribute(k_node, cudaFuncAttributeMaxDynamicSharedMemorySize, smem_bytes);

    k_zero<<<(N_NODES * D / 4 + 255) / 256, 256>>>();
    k_prep<<<48, 256>>>(Wg, Wr, Wi);
    k_edge<<<(N_EDGES * 16) / 256, 256>>>(node_feats, src, dst);
    k_node<<<(N_NODES + TILE_M - 1) / TILE_M, 256, smem_bytes>>>(node_feats, gid, bg, br, bi);
    k_final<<<N_GRAPHS, 64>>>(Wo, bo, Wp, bp, out);
}

// round 14
// speedup vs baseline: 1.3085x; 1.1850x over previous
#include <cuda_runtime.h>
#include <cuda_fp16.h>
#include <cuda_bf16.h>
#include <cstdint>

#define N_NODES  100000
#define N_EDGES  1200000
#define D        64
#define N_GRAPHS 256
#define TILE_M   128
#define LDA      68    // fp32 smem leading dim for h1 tile (conflict-free)

// ---------------- scratch (device globals; no allocation allowed) ----------
__device__ uint4    g_xh4[N_NODES * 8];    // node_feats as fp16 (12.8 MB)
__device__ uint4    g_aggh4[N_NODES * 8];  // fp16 aggregate (12.8 MB)
__device__ float    g_S[N_GRAPHS * D];     // per-graph sum of h2
__device__ int      g_cnt[N_GRAPHS];       // nodes per graph
__device__ uint32_t g_Wp[3 * 4096];        // packed bf16 (hi<<16|lo), XOR-swizzled

// ---------------- helpers ---------------------------------------------------
__device__ __forceinline__ uint32_t f2tf(float x) {
    uint32_t r; asm("cvt.rna.tf32.f32 %0, %1;" : "=r"(r) : "f"(x)); return r;
}
__device__ __forceinline__ void mma8(float* c, const uint32_t* a, uint32_t b0, uint32_t b1) {
    asm volatile("mma.sync.aligned.m16n8k8.row.col.f32.tf32.tf32.f32 "
                 "{%0,%1,%2,%3}, {%4,%5,%6,%7}, {%8,%9}, {%0,%1,%2,%3};"
                 : "+f"(c[0]), "+f"(c[1]), "+f"(c[2]), "+f"(c[3])
                 : "r"(a[0]), "r"(a[1]), "r"(a[2]), "r"(a[3]), "r"(b0), "r"(b1));
}

// ---------------- zero scratch ----------------------------------------------
__global__ void k_zero() {
    int i = blockIdx.x * blockDim.x + threadIdx.x;
    if (i < N_NODES * 8) g_aggh4[i] = make_uint4(0u, 0u, 0u, 0u);
    if (i < N_GRAPHS * D / 4)
        reinterpret_cast<float4*>(g_S)[i] = make_float4(0.f, 0.f, 0.f, 0.f);
    if (i < N_GRAPHS) g_cnt[i] = 0;
}

// ---------------- weight prep: bf16 hi/lo pack + XOR bank swizzle -----------
// g_Wp[sel*4096 + k*64 + j] = pack(W[k][ j ^ ((k&3)<<3) ])
__global__ void k_prepw(const float* __restrict__ Wg, const float* __restrict__ Wr,
                        const float* __restrict__ Wi) {
    int i = blockIdx.x * blockDim.x + threadIdx.x;
    if (i >= 3 * 4096) return;
    int sel = i >> 12, j = i & 4095;
    int k = j >> 6, n0 = j & 63;
    int n = n0 ^ ((k & 3) << 3);
    const float* W = sel == 0 ? Wg : (sel == 1 ? Wr : Wi);
    float w = W[k * 64 + n];
    __nv_bfloat16 hb = __float2bfloat16(w);
    float hf = __bfloat162float(hb);
    __nv_bfloat16 lb = __float2bfloat16(w - hf);
    g_Wp[i] = (((uint32_t)__bfloat16_as_ushort(hb)) << 16) |
              (uint32_t)__bfloat16_as_ushort(lb);
}

// ---------------- x -> fp16 -------------------------------------------------
__global__ void k_prepx(const float* __restrict__ x) {
    int i = blockIdx.x * blockDim.x + threadIdx.x;
    if (i >= N_NODES * 32) return;
    float2 f = reinterpret_cast<const float2*>(x)[i];
    reinterpret_cast<__half2*>(g_xh4)[i] = __float22half2_rn(f);
}

// ---------------- edge scatter: agg_h[dst] += xh[src]  (fp16) ---------------
// 8 lanes per edge; one uint4 (8 halves) per lane; fp16x2 vector reduction.
__global__ void k_edge(const int* __restrict__ src, const int* __restrict__ dst) {
    int t = blockIdx.x * blockDim.x + threadIdx.x;
    int e = t >> 3;
    int l = t & 7;
    if (e >= N_EDGES) return;
    int s = __ldg(&src[e]);
    int d = __ldg(&dst[e]);
    uint4 v = g_xh4[(size_t)s * 8 + l];
    uint4* a = &g_aggh4[(size_t)d * 8 + l];
    asm volatile("red.global.add.noftz.v4.f16x2 [%0], {%1, %2, %3, %4};"
                 :: "l"(a), "r"(v.x), "r"(v.y), "r"(v.z), "r"(v.w) : "memory");
}

// ---------------- fused node pipeline (tensor cores) ------------------------
// h1 = relu(agg@Wg + bg) + relu(x@Wr + br) ; h2 = relu(h1@Wi + bi)
// S[graph] += h2 ; cnt[graph] += 1
// 256 thr / 8 warps, 128-node tile, warp w owns rows [16w,16w+16).
// Weights: packed bf16 hi/lo in smem (swizzled). agg & x A-frags read
// directly from fp16 globals (L2-resident, exact in tf32).
__global__ void __launch_bounds__(256, 2) k_node(
        const int* __restrict__ gid,
        const float* __restrict__ bg, const float* __restrict__ br,
        const float* __restrict__ bi) {
    extern __shared__ float sm[];
    uint32_t* sW = (uint32_t*)sm;                  // 3*4096 packed weights
    float*    sH = sm + 3 * 4096;                  // TILE_M * LDA (h1 buffer)
    float*    sb = sH + TILE_M * LDA;              // 3 * 64 biases

    const int tid = threadIdx.x;
    const int node0 = blockIdx.x * TILE_M;

    // packed weights -> smem (uint4 copies)
    #pragma unroll
    for (int u = tid; u < 3 * 1024; u += 256)
        reinterpret_cast<uint4*>(sW)[u] = reinterpret_cast<const uint4*>(g_Wp)[u];
    if (tid < 64) { sb[tid] = bg[tid]; sb[64 + tid] = br[tid]; sb[128 + tid] = bi[tid]; }
    __syncthreads();

    const int warp = tid >> 5, lane = tid & 31;
    const int g = lane >> 2, t = lane & 3;
    const int row0 = warp * 16 + g;                // rows row0, row0+8
    const uint32_t* sWg = sW;
    const uint32_t* sWr = sW + 4096;
    const uint32_t* sWi = sW + 2 * 4096;

    const int nA = node0 + row0, nB = nA + 8;      // global node ids of lane's rows
    const bool vA = (nA < N_NODES), vB = (nB < N_NODES);
    const __half* aggA = (const __half*)g_aggh4 + (size_t)(vA ? nA : 0) * 64;
    const __half* aggB = (const __half*)g_aggh4 + (size_t)(vB ? nB : 0) * 64;
    const __half* xA   = (const __half*)g_xh4   + (size_t)(vA ? nA : 0) * 64;
    const __half* xB   = (const __half*)g_xh4   + (size_t)(vB ? nB : 0) * 64;

    // ---- GEMM1 (dual): acc1 = agg@Wg, acc2 = x@Wr ----
    float acc1[8][4], acc2[8][4];
    #pragma unroll
    for (int na = 0; na < 8; na++)
        #pragma unroll
        for (int j = 0; j < 4; j++) { acc1[na][j] = 0.f; acc2[na][j] = 0.f; }

    #pragma unroll
    for (int k0 = 0; k0 < 64; k0 += 8) {
        uint32_t aA[4], aX[4];
        aA[0] = f2tf(__half2float(__ldg(&aggA[k0 + t])));
        aA[1] = f2tf(__half2float(__ldg(&aggB[k0 + t])));
        aA[2] = f2tf(__half2float(__ldg(&aggA[k0 + t + 4])));
        aA[3] = f2tf(__half2float(__ldg(&aggB[k0 + t + 4])));
        aX[0] = f2tf(__half2float(__ldg(&xA[k0 + t])));
        aX[1] = f2tf(__half2float(__ldg(&xB[k0 + t])));
        aX[2] = f2tf(__half2float(__ldg(&xA[k0 + t + 4])));
        aX[3] = f2tf(__half2float(__ldg(&xB[k0 + t + 4])));
        #pragma unroll
        for (int na = 0; na < 8; na++) {
            int col = ((na ^ t) << 3) + g;         // swizzled column
            uint32_t wg0 = sWg[(k0 + t) * 64 + col];
            uint32_t wg1 = sWg[(k0 + t + 4) * 64 + col];
            uint32_t wr0 = sWr[(k0 + t) * 64 + col];
            uint32_t wr1 = sWr[(k0 + t + 4) * 64 + col];
            mma8(acc1[na], aA, wg0 & 0xFFFF0000u, wg1 & 0xFFFF0000u);
            mma8(acc1[na], aA, wg0 << 16,         wg1 << 16);
            mma8(acc2[na], aX, wr0 & 0xFFFF0000u, wr1 & 0xFFFF0000u);
            mma8(acc2[na], aX, wr0 << 16,         wr1 << 16);
        }
    }

    // ---- epilogue1: h1 = relu(acc1+bg) + relu(acc2+br) -> sH (own band) ----
    #pragma unroll
    for (int na = 0; na < 8; na++) {
        int c0 = na * 8 + 2 * t, c1 = c0 + 1;
        float v0 = fmaxf(acc1[na][0] + sb[c0], 0.f) + fmaxf(acc2[na][0] + sb[64 + c0], 0.f);
        float v1 = fmaxf(acc1[na][1] + sb[c1], 0.f) + fmaxf(acc2[na][1] + sb[64 + c1], 0.f);
        float v2 = fmaxf(acc1[na][2] + sb[c0], 0.f) + fmaxf(acc2[na][2] + sb[64 + c0], 0.f);
        float v3 = fmaxf(acc1[na][3] + sb[c1], 0.f) + fmaxf(acc2[na][3] + sb[64 + c1], 0.f);
        *reinterpret_cast<float2*>(&sH[row0 * LDA + c0])       = make_float2(v0, v1);
        *reinterpret_cast<float2*>(&sH[(row0 + 8) * LDA + c0]) = make_float2(v2, v3);
    }
    __syncwarp();

    // ---- GEMM2: h2 = relu(h1@Wi + bi) ----
    float acc[8][4];
    #pragma unroll
    for (int na = 0; na < 8; na++)
        #pragma unroll
        for (int j = 0; j < 4; j++) acc[na][j] = 0.f;

    #pragma unroll
    for (int k0 = 0; k0 < 64; k0 += 8) {
        uint32_t aH[4];
        aH[0] = f2tf(sH[row0 * LDA + k0 + t]);
        aH[1] = f2tf(sH[(row0 + 8) * LDA + k0 + t]);
        aH[2] = f2tf(sH[row0 * LDA + k0 + t + 4]);
        aH[3] = f2tf(sH[(row0 + 8) * LDA + k0 + t + 4]);
        #pragma unroll
        for (int na = 0; na < 8; na++) {
            int col = ((na ^ t) << 3) + g;
            uint32_t wi0 = sWi[(k0 + t) * 64 + col];
            uint32_t wi1 = sWi[(k0 + t + 4) * 64 + col];
            mma8(acc[na], aH, wi0 & 0xFFFF0000u, wi1 & 0xFFFF0000u);
            mma8(acc[na], aH, wi0 << 16,         wi1 << 16);
        }
    }

    // ---- epilogue2: scatter h2 into per-graph sums ----
    int gdA = vA ? __ldg(&gid[nA]) : 0;
    int gdB = vB ? __ldg(&gid[nB]) : 0;
    #pragma unroll
    for (int na = 0; na < 8; na++) {
        int c0 = na * 8 + 2 * t, c1 = c0 + 1;
        if (vA) {
            float p0 = fmaxf(acc[na][0] + sb[128 + c0], 0.f);
            float p1 = fmaxf(acc[na][1] + sb[128 + c1], 0.f);
            asm volatile("red.global.add.v2.f32 [%0], {%1, %2};"
                         :: "l"(&g_S[gdA * 64 + c0]), "f"(p0), "f"(p1) : "memory");
        }
        if (vB) {
            float p2 = fmaxf(acc[na][2] + sb[128 + c0], 0.f);
            float p3 = fmaxf(acc[na][3] + sb[128 + c1], 0.f);
            asm volatile("red.global.add.v2.f32 [%0], {%1, %2};"
                         :: "l"(&g_S[gdB * 64 + c0]), "f"(p2), "f"(p3) : "memory");
        }
    }
    if (t == 0) {
        if (vA) atomicAdd(&g_cnt[gdA], 1);
        if (vB) atomicAdd(&g_cnt[gdB], 1);
    }
}

// ---------------- final readout ---------------------------------------------
// out[g] = S[g] . (W_out @ W_pred) + cnt[g] * (b_out . W_pred) + b_pred
__global__ void __launch_bounds__(64) k_final(const float* __restrict__ Wo,
                                              const float* __restrict__ bo,
                                              const float* __restrict__ Wp,
                                              const float* __restrict__ bp,
                                              float* __restrict__ out) {
    __shared__ float red[4];
    int gr = blockIdx.x, k = threadIdx.x;   // k in [0,64)
    float wop = 0.f;
    #pragma unroll 16
    for (int m = 0; m < 128; m++) wop += __ldg(&Wo[k * 128 + m]) * __ldg(&Wp[m]);
    float p  = g_S[gr * 64 + k] * wop;
    float sc = bo[k] * Wp[k] + bo[k + 64] * Wp[k + 64];
    #pragma unroll
    for (int o = 16; o; o >>= 1) {
        p  += __shfl_xor_sync(0xffffffffu, p, o);
        sc += __shfl_xor_sync(0xffffffffu, sc, o);
    }
    if ((k & 31) == 0) { red[(k >> 5) * 2] = p; red[(k >> 5) * 2 + 1] = sc; }
    __syncthreads();
    if (k == 0)
        out[gr] = red[0] + red[2] + (float)g_cnt[gr] * (red[1] + red[3]) + bp[0];
}

// ---------------- launch ----------------------------------------------------
extern "C" void kernel_launch(void* const* d_in, const int* in_sizes, int n_in,
                              void* d_out, int out_size) {
    const float* node_feats = (const float*)d_in[0];
    // d_in[1] = edge_feats (unused by the reference)
    const int*   src = (const int*)d_in[2];
    const int*   dst = (const int*)d_in[3];
    const int*   gid = (const int*)d_in[4];
    const float* Wg  = (const float*)d_in[5];
    const float* bg  = (const float*)d_in[6];
    const float* Wr  = (const float*)d_in[7];
    const float* br  = (const float*)d_in[8];
    const float* Wi  = (const float*)d_in[9];
    const float* bi  = (const float*)d_in[10];
    const float* Wo  = (const float*)d_in[11];
    const float* bo  = (const float*)d_in[12];
    const float* Wp  = (const float*)d_in[13];
    const float* bp  = (const float*)d_in[14];
    float* out = (float*)d_out;

    const int smem_bytes = 3 * 4096 * 4 + TILE_M * LDA * 4 + 192 * 4;
    cudaFuncSetAttribute(k_node, cudaFuncAttributeMaxDynamicSharedMemorySize, smem_bytes);

    k_zero <<<(N_NODES * 8 + 255) / 256, 256>>>();
    k_prepw<<<48, 256>>>(Wg, Wr, Wi);
    k_prepx<<<(N_NODES * 32 + 255) / 256, 256>>>(node_feats);
    k_edge <<<(N_EDGES * 8 + 255) / 256, 256>>>(src, dst);
    k_node <<<(N_NODES + TILE_M - 1) / TILE_M, 256, smem_bytes>>>(gid, bg, br, bi);
    k_final<<<N_GRAPHS, 64>>>(Wo, bo, Wp, bp, out);
}